// round 9
// baseline (speedup 1.0000x reference)
#include <cuda_runtime.h>
#include <math.h>

#define B_  2
#define S_  2048
#define DM_ 1024
#define H_  16
#define D_  64

// Scratch. g_q/g_k: fp32 after gemm, tf32 bits after rope.
// g_v: tf32 bits directly from gemm epilogue.
__device__ float g_q[B_*H_*S_*D_];
__device__ float g_k[B_*H_*S_*D_];
__device__ float g_v[B_*H_*S_*D_];

// --------------------------------------------------------------------------
__device__ __forceinline__ unsigned f2tf(float x) {
    unsigned u;
    asm("cvt.rna.tf32.f32 %0, %1;" : "=r"(u) : "f"(x));
    return u;
}

__device__ __forceinline__ void mma_tf32(float d[4], const unsigned a[4],
                                         unsigned b0, unsigned b1,
                                         const float c[4]) {
    asm volatile(
        "mma.sync.aligned.m16n8k8.row.col.f32.tf32.tf32.f32 "
        "{%0,%1,%2,%3}, {%4,%5,%6,%7}, {%8,%9}, {%10,%11,%12,%13};"
        : "=f"(d[0]), "=f"(d[1]), "=f"(d[2]), "=f"(d[3])
        : "r"(a[0]), "r"(a[1]), "r"(a[2]), "r"(a[3]),
          "r"(b0), "r"(b1),
          "f"(c[0]), "f"(c[1]), "f"(c[2]), "f"(c[3]));
}

__device__ __forceinline__ void cp_async16(unsigned saddr, const void* gptr) {
    asm volatile("cp.async.cg.shared.global [%0], [%1], 16;"
                 :: "r"(saddr), "l"(gptr));
}

// --------------------------------------------------------------------------
// Kernel 1: P[m,n] = sum_k X[m,k] * W[n,k], tf32 MMA.
// Block tile 128x128, 128 threads, 4 warps (2m x 2n), warp tile 64x64.
// k-step 16, double-buffered SMEM, register-staged pipeline, 1 sync/step.
// V output (z==2) stored as tf32 bits.
// --------------------------------------------------------------------------
__global__ __launch_bounds__(128)
void qkv_gemm(const float* __restrict__ X,
              const float* __restrict__ Wq,
              const float* __restrict__ Wk,
              const float* __restrict__ Wv)
{
    __shared__ unsigned As[2][128][20];
    __shared__ unsigned Bs[2][128][20];

    const float* W; float* out; int isv = 0;
    if (blockIdx.z == 0)      { W = Wq; out = g_q; }
    else if (blockIdx.z == 1) { W = Wk; out = g_k; }
    else                      { W = Wv; out = g_v; isv = 1; }

    const int tid  = threadIdx.x;
    const int lane = tid & 31;
    const int wid  = tid >> 5;
    const int wm   = wid & 1;     // m offset wm*64
    const int wn   = wid >> 1;    // n offset wn*64
    const int g    = lane >> 2;
    const int l4   = lane & 3;

    const int m0 = blockIdx.y * 128;
    const int n0 = blockIdx.x * 128;

    const float* Ap = X + (size_t)(m0 + tid) * DM_;
    const float* Bp = W + (size_t)(n0 + tid) * DM_;

    float acc[4][8][4];
    #pragma unroll
    for (int mt = 0; mt < 4; mt++)
        #pragma unroll
        for (int nt = 0; nt < 8; nt++)
            #pragma unroll
            for (int i = 0; i < 4; i++) acc[mt][nt][i] = 0.f;

    float4 av[4], bv[4];
    #pragma unroll
    for (int i = 0; i < 4; i++) {
        av[i] = *(const float4*)(Ap + i * 4);
        bv[i] = *(const float4*)(Bp + i * 4);
    }
    #pragma unroll
    for (int i = 0; i < 4; i++) {
        uint4 ta = make_uint4(f2tf(av[i].x), f2tf(av[i].y),
                              f2tf(av[i].z), f2tf(av[i].w));
        *(uint4*)&As[0][tid][i*4] = ta;
        uint4 tb = make_uint4(f2tf(bv[i].x), f2tf(bv[i].y),
                              f2tf(bv[i].z), f2tf(bv[i].w));
        *(uint4*)&Bs[0][tid][i*4] = tb;
    }
    __syncthreads();

    #pragma unroll 2
    for (int s = 0; s < 64; s++) {
        if (s < 63) {
            const float* Ap2 = Ap + (s + 1) * 16;
            const float* Bp2 = Bp + (s + 1) * 16;
            #pragma unroll
            for (int i = 0; i < 4; i++) {
                av[i] = *(const float4*)(Ap2 + i * 4);
                bv[i] = *(const float4*)(Bp2 + i * 4);
            }
        }
        const unsigned (*Ab)[20] = As[s & 1];
        const unsigned (*Bb)[20] = Bs[s & 1];
        #pragma unroll
        for (int kk = 0; kk < 2; kk++) {
            const int c = kk * 8 + l4;
            unsigned a[4][4];
            #pragma unroll
            for (int mt = 0; mt < 4; mt++) {
                int r = wm * 64 + mt * 16 + g;
                a[mt][0] = Ab[r][c];     a[mt][1] = Ab[r + 8][c];
                a[mt][2] = Ab[r][c + 4]; a[mt][3] = Ab[r + 8][c + 4];
            }
            #pragma unroll
            for (int nt = 0; nt < 8; nt++) {
                int n = wn * 64 + nt * 8 + g;
                unsigned b0 = Bb[n][c];
                unsigned b1 = Bb[n][c + 4];
                #pragma unroll
                for (int mt = 0; mt < 4; mt++)
                    mma_tf32(acc[mt][nt], a[mt], b0, b1, acc[mt][nt]);
            }
        }
        if (s < 63) {
            int nb = (s + 1) & 1;
            #pragma unroll
            for (int i = 0; i < 4; i++) {
                uint4 ta = make_uint4(f2tf(av[i].x), f2tf(av[i].y),
                                      f2tf(av[i].z), f2tf(av[i].w));
                *(uint4*)&As[nb][tid][i*4] = ta;
                uint4 tb = make_uint4(f2tf(bv[i].x), f2tf(bv[i].y),
                                      f2tf(bv[i].z), f2tf(bv[i].w));
                *(uint4*)&Bs[nb][tid][i*4] = tb;
            }
            __syncthreads();
        }
    }

    // Epilogue: scatter to [B,H,S,D]; V as tf32 bits.
    #pragma unroll
    for (int mt = 0; mt < 4; mt++) {
        #pragma unroll
        for (int half = 0; half < 2; half++) {
            int mm = m0 + wm * 64 + mt * 16 + g + half * 8;
            int bb = mm >> 11;
            int ss = mm & (S_ - 1);
            #pragma unroll
            for (int nt = 0; nt < 8; nt++) {
                int n  = n0 + wn * 64 + nt * 8 + l4 * 2;
                int hh = n >> 6;
                int dd = n & 63;
                float v0 = acc[mt][nt][half*2 + 0];
                float v1 = acc[mt][nt][half*2 + 1];
                float2 v;
                if (isv) v = make_float2(__uint_as_float(f2tf(v0)),
                                         __uint_as_float(f2tf(v1)));
                else     v = make_float2(v0, v1);
                *(float2*)&out[(((size_t)(bb*H_ + hh))*S_ + ss)*D_ + dd] = v;
            }
        }
    }
}

// --------------------------------------------------------------------------
// Kernel 2: RoPE in-place on g_q/g_k; Q scaled by 1/8; outputs tf32 bits.
// --------------------------------------------------------------------------
__global__ __launch_bounds__(256)
void rope_kernel(const int* __restrict__ pos_ids)
{
    int idx = blockIdx.x * blockDim.x + threadIdx.x;
    const int total = B_ * H_ * S_ * 32;
    if (idx >= total) return;

    int d2 = idx & 31;
    int s  = (idx >> 5) & (S_ - 1);
    int b  = idx >> 20;

    int pos = pos_ids[b * S_ + s];
    float inv = (float)exp(-(double)d2 * (log(10000.0) / 32.0));
    float ang = (float)pos * inv;
    float sn, cs;
    sincosf(ang, &sn, &cs);

    int base = (idx >> 5) << 6;

    float q1 = g_q[base + d2];
    float q2 = g_q[base + 32 + d2];
    g_q[base + d2]      = __uint_as_float(f2tf(0.125f * (q1 * cs - q2 * sn)));
    g_q[base + 32 + d2] = __uint_as_float(f2tf(0.125f * (q2 * cs + q1 * sn)));

    float k1 = g_k[base + d2];
    float k2 = g_k[base + 32 + d2];
    g_k[base + d2]      = __uint_as_float(f2tf(k1 * cs - k2 * sn));
    g_k[base + 32 + d2] = __uint_as_float(f2tf(k2 * cs + k1 * sn));
}

// --------------------------------------------------------------------------
// Kernel 3: flash attention, tf32 MMA, cp.async double-buffered K/V.
// 128 threads (4 warps), q-tile 64, k-tile 64. K and V row-major in SMEM
// (pad 68 -> conflict-free scalar B-fragment LDS for both). P stays in
// registers (quad-shuffle transpose). Dynamic SMEM = 4*64*68*4 = 69632 B.
// --------------------------------------------------------------------------
#define KV_WORDS (64 * 68)

__global__ __launch_bounds__(128)
void attn_tf32(const float* __restrict__ mask, float* __restrict__ outp)
{
    extern __shared__ unsigned smA[];   // [K0 | K1 | V0 | V1], each KV_WORDS

    const int tid  = threadIdx.x;
    const int lane = tid & 31;
    const int wid  = tid >> 5;
    const int g    = lane >> 2;
    const int l4   = lane & 3;

    const int b  = blockIdx.z;
    const int h  = blockIdx.y;
    const int q0 = blockIdx.x * 64;

    const unsigned* Qg = (const unsigned*)g_q + (((size_t)(b*H_ + h))*S_ + q0) * D_;
    const uint4* Kg4 = (const uint4*)(g_k + (((size_t)(b*H_ + h))*S_) * D_);
    const uint4* Vg4 = (const uint4*)(g_v + (((size_t)(b*H_ + h))*S_) * D_);
    const float* Mg  = mask + ((size_t)b * S_ + q0) * S_;

    const int r0 = wid * 16 + g;

    // Q A-fragments (already tf32 bits)
    unsigned qa[8][4];
    #pragma unroll
    for (int kk = 0; kk < 8; kk++) {
        qa[kk][0] = Qg[(size_t)r0       * D_ + kk*8 + l4];
        qa[kk][1] = Qg[(size_t)(r0 + 8) * D_ + kk*8 + l4];
        qa[kk][2] = Qg[(size_t)r0       * D_ + kk*8 + l4 + 4];
        qa[kk][3] = Qg[(size_t)(r0 + 8) * D_ + kk*8 + l4 + 4];
    }

    const unsigned sbase = (unsigned)__cvta_generic_to_shared(smA);
    const int kr = tid >> 1;            // 0..63 row
    const int cw = (tid & 1) * 8;       // uint4 col offset 0 / 8
    const unsigned soff = (unsigned)(kr * 68 + cw * 4) * 4u;  // byte off in region

    // prologue: tile 0 -> buffer 0
    {
        int roff = kr * 16 + cw;
        #pragma unroll
        for (int i = 0; i < 8; i++) {
            cp_async16(sbase + soff + i*16,                      Kg4 + roff + i);
            cp_async16(sbase + 2u*KV_WORDS*4u + soff + i*16,     Vg4 + roff + i);
        }
        asm volatile("cp.async.commit_group;");
    }

    float o[8][4];
    #pragma unroll
    for (int nt = 0; nt < 8; nt++)
        #pragma unroll
        for (int i = 0; i < 4; i++) o[nt][i] = 0.f;
    float m0r = -1e30f, m1r = -1e30f, l0r = 0.f, l1r = 0.f;

    for (int t = 0; t < S_ / 64; t++) {
        if (t < S_ / 64 - 1) {
            int nb = (t + 1) & 1;
            int roff = ((t + 1) * 64 + kr) * 16 + cw;
            unsigned kadd = sbase + (unsigned)nb * KV_WORDS * 4u + soff;
            unsigned vadd = sbase + (2u + (unsigned)nb) * KV_WORDS * 4u + soff;
            #pragma unroll
            for (int i = 0; i < 8; i++) {
                cp_async16(kadd + i*16, Kg4 + roff + i);
                cp_async16(vadd + i*16, Vg4 + roff + i);
            }
        }
        asm volatile("cp.async.commit_group;");
        asm volatile("cp.async.wait_group 1;");
        __syncthreads();

        const unsigned* KSp = smA + (t & 1) * KV_WORDS;
        const unsigned* VSp = smA + (2 + (t & 1)) * KV_WORDS;
        const int kbase = t * 64;

        // ---- S = Q K^T ----
        float s[8][4];
        #pragma unroll
        for (int nt = 0; nt < 8; nt++)
            #pragma unroll
            for (int i = 0; i < 4; i++) s[nt][i] = 0.f;

        #pragma unroll
        for (int kk = 0; kk < 8; kk++) {
            const int c = kk * 8 + l4;
            #pragma unroll
            for (int nt = 0; nt < 8; nt++) {
                unsigned b0 = KSp[(nt*8 + g) * 68 + c];
                unsigned b1 = KSp[(nt*8 + g) * 68 + c + 4];
                mma_tf32(s[nt], qa[kk], b0, b1, s[nt]);
            }
        }

        // ---- mask add ----
        #pragma unroll
        for (int nt = 0; nt < 8; nt++) {
            const float* mp = Mg + (size_t)r0 * S_ + kbase + nt*8 + l4*2;
            float2 ma = *(const float2*)mp;
            float2 mb = *(const float2*)(mp + 8 * S_);
            s[nt][0] += ma.x; s[nt][1] += ma.y;
            s[nt][2] += mb.x; s[nt][3] += mb.y;
        }

        // ---- online softmax (rows r0, r0+8) ----
        float mx0 = -1e30f, mx1 = -1e30f;
        #pragma unroll
        for (int nt = 0; nt < 8; nt++) {
            mx0 = fmaxf(mx0, fmaxf(s[nt][0], s[nt][1]));
            mx1 = fmaxf(mx1, fmaxf(s[nt][2], s[nt][3]));
        }
        mx0 = fmaxf(mx0, __shfl_xor_sync(0xffffffffu, mx0, 1));
        mx0 = fmaxf(mx0, __shfl_xor_sync(0xffffffffu, mx0, 2));
        mx1 = fmaxf(mx1, __shfl_xor_sync(0xffffffffu, mx1, 1));
        mx1 = fmaxf(mx1, __shfl_xor_sync(0xffffffffu, mx1, 2));

        float mn0 = fmaxf(m0r, mx0);
        float mn1 = fmaxf(m1r, mx1);

        float sum0 = 0.f, sum1 = 0.f;
        #pragma unroll
        for (int nt = 0; nt < 8; nt++) {
            s[nt][0] = __expf(s[nt][0] - mn0);
            s[nt][1] = __expf(s[nt][1] - mn0);
            s[nt][2] = __expf(s[nt][2] - mn1);
            s[nt][3] = __expf(s[nt][3] - mn1);
            sum0 += s[nt][0] + s[nt][1];
            sum1 += s[nt][2] + s[nt][3];
        }
        sum0 += __shfl_xor_sync(0xffffffffu, sum0, 1);
        sum0 += __shfl_xor_sync(0xffffffffu, sum0, 2);
        sum1 += __shfl_xor_sync(0xffffffffu, sum1, 1);
        sum1 += __shfl_xor_sync(0xffffffffu, sum1, 2);

        float a0 = __expf(m0r - mn0);
        float a1 = __expf(m1r - mn1);
        l0r = l0r * a0 + sum0;
        l1r = l1r * a1 + sum1;
        m0r = mn0; m1r = mn1;
        #pragma unroll
        for (int nt = 0; nt < 8; nt++) {
            o[nt][0] *= a0; o[nt][1] *= a0;
            o[nt][2] *= a1; o[nt][3] *= a1;
        }

        // ---- PV: C-frag -> A-frag via quad shuffles, then mma ----
        const int src  = (lane & ~3) | (l4 >> 1);
        const int src2 = src + 2;
        const bool odd = (l4 & 1);
        #pragma unroll
        for (int kk = 0; kk < 8; kk++) {
            float v00 = __shfl_sync(0xffffffffu, s[kk][0], src);
            float v01 = __shfl_sync(0xffffffffu, s[kk][1], src);
            float v10 = __shfl_sync(0xffffffffu, s[kk][2], src);
            float v11 = __shfl_sync(0xffffffffu, s[kk][3], src);
            float w00 = __shfl_sync(0xffffffffu, s[kk][0], src2);
            float w01 = __shfl_sync(0xffffffffu, s[kk][1], src2);
            float w10 = __shfl_sync(0xffffffffu, s[kk][2], src2);
            float w11 = __shfl_sync(0xffffffffu, s[kk][3], src2);
            unsigned pa[4];
            pa[0] = f2tf(odd ? v01 : v00);
            pa[1] = f2tf(odd ? v11 : v10);
            pa[2] = f2tf(odd ? w01 : w00);
            pa[3] = f2tf(odd ? w11 : w10);

            const int c = kk * 8 + l4;
            #pragma unroll
            for (int nt = 0; nt < 8; nt++) {
                unsigned b0 = VSp[c * 68 + nt*8 + g];
                unsigned b1 = VSp[(c + 4) * 68 + nt*8 + g];
                mma_tf32(o[nt], pa, b0, b1, o[nt]);
            }
        }
        __syncthreads();   // all reads of this buffer done before t+2 overwrites
    }

    // ---- normalize + write ctx ----
    float inv0 = 1.f / l0r;
    float inv1 = 1.f / l1r;
    #pragma unroll
    for (int nt = 0; nt < 8; nt++) {
        int d = h * 64 + nt * 8 + l4 * 2;
        float2 r0v = make_float2(o[nt][0] * inv0, o[nt][1] * inv0);
        float2 r1v = make_float2(o[nt][2] * inv1, o[nt][3] * inv1);
        *(float2*)&outp[((size_t)b * S_ + q0 + r0    ) * DM_ + d] = r0v;
        *(float2*)&outp[((size_t)b * S_ + q0 + r0 + 8) * DM_ + d] = r1v;
    }
}

// --------------------------------------------------------------------------
extern "C" void kernel_launch(void* const* d_in, const int* in_sizes, int n_in,
                              void* d_out, int out_size)
{
    const float* hidden = (const float*)d_in[0];
    const float* mask   = (const float*)d_in[1];
    const int*   pos    = (const int*)  d_in[2];
    const float* Wq     = (const float*)d_in[3];
    const float* Wk     = (const float*)d_in[4];
    const float* Wv     = (const float*)d_in[5];
    float* out = (float*)d_out;

    const int attn_smem = 4 * KV_WORDS * sizeof(unsigned);  // 69632 B
    cudaFuncSetAttribute(attn_tf32,
                         cudaFuncAttributeMaxDynamicSharedMemorySize, attn_smem);

    dim3 g1(DM_ / 128, (B_ * S_) / 128, 3);
    qkv_gemm<<<g1, 128>>>(hidden, Wq, Wk, Wv);

    int total_pairs = B_ * H_ * S_ * 32;
    rope_kernel<<<(total_pairs + 255) / 256, 256>>>(pos);

    dim3 g2(S_ / 64, H_, B_);
    attn_tf32<<<g2, 128, attn_smem>>>(mask, out);
}

// round 11
// speedup vs baseline: 1.7118x; 1.7118x over previous
#include <cuda_runtime.h>
#include <math.h>

#define B_  2
#define S_  2048
#define DM_ 1024
#define H_  16
#define D_  64

// Scratch. g_q/g_k: fp32 after gemm, tf32 bits after rope. g_v: tf32 bits.
__device__ float g_q[B_*H_*S_*D_];
__device__ float g_k[B_*H_*S_*D_];
__device__ float g_v[B_*H_*S_*D_];
// Pre-converted tf32 operands for the QKV gemm.
__device__ unsigned g_xt[B_*S_*DM_];      // hidden, tf32 bits
__device__ unsigned g_wt[3*DM_*DM_];      // Wq|Wk|Wv, tf32 bits

// --------------------------------------------------------------------------
__device__ __forceinline__ unsigned f2tf(float x) {
    unsigned u;
    asm("cvt.rna.tf32.f32 %0, %1;" : "=r"(u) : "f"(x));
    return u;
}

__device__ __forceinline__ void mma_tf32(float d[4], const unsigned a[4],
                                         unsigned b0, unsigned b1,
                                         const float c[4]) {
    asm volatile(
        "mma.sync.aligned.m16n8k8.row.col.f32.tf32.tf32.f32 "
        "{%0,%1,%2,%3}, {%4,%5,%6,%7}, {%8,%9}, {%10,%11,%12,%13};"
        : "=f"(d[0]), "=f"(d[1]), "=f"(d[2]), "=f"(d[3])
        : "r"(a[0]), "r"(a[1]), "r"(a[2]), "r"(a[3]),
          "r"(b0), "r"(b1),
          "f"(c[0]), "f"(c[1]), "f"(c[2]), "f"(c[3]));
}

__device__ __forceinline__ void cp_async16(unsigned saddr, const void* gptr) {
    asm volatile("cp.async.cg.shared.global [%0], [%1], 16;"
                 :: "r"(saddr), "l"(gptr));
}

// --------------------------------------------------------------------------
// Kernel 0: convert hidden + W to tf32 bits.
// --------------------------------------------------------------------------
__global__ __launch_bounds__(256)
void prep_tf32(const float* __restrict__ X,
               const float* __restrict__ Wq,
               const float* __restrict__ Wk,
               const float* __restrict__ Wv)
{
    int idx = blockIdx.x * blockDim.x + threadIdx.x;
    const int NX = B_*S_*DM_;       // 4M
    const int NW = DM_*DM_;         // 1M
    if (idx < NX) g_xt[idx] = f2tf(X[idx]);
    if (idx < NW) {
        g_wt[idx]        = f2tf(Wq[idx]);
        g_wt[NW + idx]   = f2tf(Wk[idx]);
        g_wt[2*NW + idx] = f2tf(Wv[idx]);
    }
}

// --------------------------------------------------------------------------
// Kernel 1: P[m,n] = sum_k X[m,k] * W[n,k], tf32 MMA, from pre-converted.
// 256 threads, 8 warps (4m x 2n), warp tile 32x64, k-step 16,
// 3-stage cp.async pipeline. V output stored as tf32 bits.
// --------------------------------------------------------------------------
#define GROW 20
#define GSTG_WORDS (128 * GROW)

__global__ __launch_bounds__(256, 2)
void qkv_gemm()
{
    extern __shared__ unsigned sh[];            // As[3][128][20] | Bs[3][128][20]
    const unsigned* As = sh;
    const unsigned* Bs = sh + 3 * GSTG_WORDS;

    const int z = blockIdx.z;
    float* out = (z == 0) ? g_q : (z == 1 ? g_k : g_v);
    const int isv = (z == 2);
    const unsigned* Wt = g_wt + (size_t)z * (DM_*DM_);

    const int tid  = threadIdx.x;
    const int lane = tid & 31;
    const int wid  = tid >> 5;
    const int wm   = wid & 3;       // m offset wm*32
    const int wn   = wid >> 2;      // n offset wn*64
    const int g    = lane >> 2;
    const int l4   = lane & 3;

    const int m0 = blockIdx.y * 128;
    const int n0 = blockIdx.x * 128;

    // cp.async mapping: row = tid>>1 (0..127), word col = (tid&1)*8, 2x16B
    const int lrow = tid >> 1;
    const int lcol = (tid & 1) * 8;
    const unsigned* Ag = g_xt + (size_t)(m0 + lrow) * DM_ + lcol;
    const unsigned* Bg = Wt   + (size_t)(n0 + lrow) * DM_ + lcol;
    const unsigned sbase = (unsigned)__cvta_generic_to_shared(sh);
    const unsigned sAoff = sbase + (unsigned)(lrow * GROW + lcol) * 4u;
    const unsigned sBoff = sAoff + 3u * GSTG_WORDS * 4u;

    float acc[2][8][4];
    #pragma unroll
    for (int mt = 0; mt < 2; mt++)
        #pragma unroll
        for (int nt = 0; nt < 8; nt++)
            #pragma unroll
            for (int i = 0; i < 4; i++) acc[mt][nt][i] = 0.f;

    // prologue: stages 0,1
    #pragma unroll
    for (int st = 0; st < 2; st++) {
        unsigned off = (unsigned)st * GSTG_WORDS * 4u;
        int k0 = st * 16;
        cp_async16(sAoff + off,      Ag + k0);
        cp_async16(sAoff + off + 16, Ag + k0 + 4);
        cp_async16(sBoff + off,      Bg + k0);
        cp_async16(sBoff + off + 16, Bg + k0 + 4);
        asm volatile("cp.async.commit_group;");
    }

    for (int t = 0; t < 64; t++) {
        asm volatile("cp.async.wait_group 1;");
        __syncthreads();

        const unsigned* Ab = As + (t % 3) * GSTG_WORDS;
        const unsigned* Bb = Bs + (t % 3) * GSTG_WORDS;

        #pragma unroll
        for (int kk = 0; kk < 2; kk++) {
            const int c = kk * 8 + l4;
            unsigned a[2][4];
            #pragma unroll
            for (int mt = 0; mt < 2; mt++) {
                int r = wm * 32 + mt * 16 + g;
                a[mt][0] = Ab[r * GROW + c];
                a[mt][1] = Ab[(r + 8) * GROW + c];
                a[mt][2] = Ab[r * GROW + c + 4];
                a[mt][3] = Ab[(r + 8) * GROW + c + 4];
            }
            #pragma unroll
            for (int nt = 0; nt < 8; nt++) {
                int n = wn * 64 + nt * 8 + g;
                unsigned b0 = Bb[n * GROW + c];
                unsigned b1 = Bb[n * GROW + c + 4];
                mma_tf32(acc[0][nt], a[0], b0, b1, acc[0][nt]);
                mma_tf32(acc[1][nt], a[1], b0, b1, acc[1][nt]);
            }
        }
        __syncthreads();

        if (t + 2 < 64) {
            int st = (t + 2) % 3;
            unsigned off = (unsigned)st * GSTG_WORDS * 4u;
            int k0 = (t + 2) * 16;
            cp_async16(sAoff + off,      Ag + k0);
            cp_async16(sAoff + off + 16, Ag + k0 + 4);
            cp_async16(sBoff + off,      Bg + k0);
            cp_async16(sBoff + off + 16, Bg + k0 + 4);
        }
        asm volatile("cp.async.commit_group;");
    }

    // Epilogue: scatter to [B,H,S,D]; V as tf32 bits.
    #pragma unroll
    for (int mt = 0; mt < 2; mt++) {
        #pragma unroll
        for (int half = 0; half < 2; half++) {
            int mm = m0 + wm * 32 + mt * 16 + g + half * 8;
            int bb = mm >> 11;
            int ss = mm & (S_ - 1);
            #pragma unroll
            for (int nt = 0; nt < 8; nt++) {
                int n  = n0 + wn * 64 + nt * 8 + l4 * 2;
                int hh = n >> 6;
                int dd = n & 63;
                float v0 = acc[mt][nt][half*2 + 0];
                float v1 = acc[mt][nt][half*2 + 1];
                float2 v;
                if (isv) v = make_float2(__uint_as_float(f2tf(v0)),
                                         __uint_as_float(f2tf(v1)));
                else     v = make_float2(v0, v1);
                *(float2*)&out[(((size_t)(bb*H_ + hh))*S_ + ss)*D_ + dd] = v;
            }
        }
    }
}

// --------------------------------------------------------------------------
// Kernel 2: RoPE in-place on g_q/g_k; Q scaled by 1/8; outputs tf32 bits.
// --------------------------------------------------------------------------
__global__ __launch_bounds__(256)
void rope_kernel(const int* __restrict__ pos_ids)
{
    int idx = blockIdx.x * blockDim.x + threadIdx.x;
    const int total = B_ * H_ * S_ * 32;
    if (idx >= total) return;

    int d2 = idx & 31;
    int s  = (idx >> 5) & (S_ - 1);
    int b  = idx >> 20;

    int pos = pos_ids[b * S_ + s];
    float inv = (float)exp(-(double)d2 * (log(10000.0) / 32.0));
    float ang = (float)pos * inv;
    float sn, cs;
    sincosf(ang, &sn, &cs);

    int base = (idx >> 5) << 6;

    float q1 = g_q[base + d2];
    float q2 = g_q[base + 32 + d2];
    g_q[base + d2]      = __uint_as_float(f2tf(0.125f * (q1 * cs - q2 * sn)));
    g_q[base + 32 + d2] = __uint_as_float(f2tf(0.125f * (q2 * cs + q1 * sn)));

    float k1 = g_k[base + d2];
    float k2 = g_k[base + 32 + d2];
    g_k[base + d2]      = __uint_as_float(f2tf(k1 * cs - k2 * sn));
    g_k[base + 32 + d2] = __uint_as_float(f2tf(k2 * cs + k1 * sn));
}

// --------------------------------------------------------------------------
// Kernel 3: flash attention, tf32 MMA (pre-converted inputs).
// 128 threads (4 warps), q-tile 64, k-tile 64.
// Ks[kpos][d] pad 68: QK B-frag read Ks[nt*8+g][c], bank 4g+l4 -> distinct.
// Vs[kpos][d] pad 72: PV B-frag read Vs[c][nt*8+g], bank 8*l4+g -> distinct.
// Both stored row-major with vectorized uint4 stores. P stays in registers
// via quad-shuffle transpose. Static SMEM = 64*(68+72)*4 = 35840 B.
// --------------------------------------------------------------------------
__global__ __launch_bounds__(128)
void attn_tf32(const float* __restrict__ mask, float* __restrict__ outp)
{
    __shared__ unsigned Ks[64][68];
    __shared__ unsigned Vs[64][72];

    const int tid  = threadIdx.x;
    const int lane = tid & 31;
    const int wid  = tid >> 5;
    const int g    = lane >> 2;
    const int l4   = lane & 3;

    const int b  = blockIdx.z;
    const int h  = blockIdx.y;
    const int q0 = blockIdx.x * 64;

    const unsigned* Qg = (const unsigned*)g_q + (((size_t)(b*H_ + h))*S_ + q0) * D_;
    const uint4* Kg4 = (const uint4*)(g_k + (((size_t)(b*H_ + h))*S_) * D_);
    const uint4* Vg4 = (const uint4*)(g_v + (((size_t)(b*H_ + h))*S_) * D_);
    const float* Mg  = mask + ((size_t)b * S_ + q0) * S_;

    const int r0 = wid * 16 + g;

    // Q A-fragments (already tf32 bits)
    unsigned qa[8][4];
    #pragma unroll
    for (int kk = 0; kk < 8; kk++) {
        qa[kk][0] = Qg[(size_t)r0       * D_ + kk*8 + l4];
        qa[kk][1] = Qg[(size_t)(r0 + 8) * D_ + kk*8 + l4];
        qa[kk][2] = Qg[(size_t)r0       * D_ + kk*8 + l4 + 4];
        qa[kk][3] = Qg[(size_t)(r0 + 8) * D_ + kk*8 + l4 + 4];
    }

    float o[8][4];
    #pragma unroll
    for (int nt = 0; nt < 8; nt++)
        #pragma unroll
        for (int i = 0; i < 4; i++) o[nt][i] = 0.f;
    float m0r = -1e30f, m1r = -1e30f, l0r = 0.f, l1r = 0.f;

    const int kr   = tid & 63;      // K/V row
    const int half = tid >> 6;      // d half (0: d<32, 1: d>=32)

    for (int t = 0; t < S_ / 64; t++) {
        const int kbase = t * 64;
        __syncthreads();
        {
            const uint4* Kp = Kg4 + (size_t)(kbase + kr) * (D_/4) + half * 8;
            const uint4* Vp = Vg4 + (size_t)(kbase + kr) * (D_/4) + half * 8;
            #pragma unroll
            for (int i = 0; i < 8; i++) {
                *(uint4*)&Ks[kr][half*32 + i*4] = Kp[i];
                *(uint4*)&Vs[kr][half*32 + i*4] = Vp[i];
            }
        }
        __syncthreads();

        // ---- S = Q K^T ----
        float s[8][4];
        #pragma unroll
        for (int nt = 0; nt < 8; nt++)
            #pragma unroll
            for (int i = 0; i < 4; i++) s[nt][i] = 0.f;

        #pragma unroll
        for (int kk = 0; kk < 8; kk++) {
            const int c = kk * 8 + l4;
            #pragma unroll
            for (int nt = 0; nt < 8; nt++) {
                unsigned b0 = Ks[nt*8 + g][c];
                unsigned b1 = Ks[nt*8 + g][c + 4];
                mma_tf32(s[nt], qa[kk], b0, b1, s[nt]);
            }
        }

        // ---- mask add ----
        #pragma unroll
        for (int nt = 0; nt < 8; nt++) {
            const float* mp = Mg + (size_t)r0 * S_ + kbase + nt*8 + l4*2;
            float2 ma = *(const float2*)mp;
            float2 mb = *(const float2*)(mp + 8 * S_);
            s[nt][0] += ma.x; s[nt][1] += ma.y;
            s[nt][2] += mb.x; s[nt][3] += mb.y;
        }

        // ---- online softmax (rows r0, r0+8) ----
        float mx0 = -1e30f, mx1 = -1e30f;
        #pragma unroll
        for (int nt = 0; nt < 8; nt++) {
            mx0 = fmaxf(mx0, fmaxf(s[nt][0], s[nt][1]));
            mx1 = fmaxf(mx1, fmaxf(s[nt][2], s[nt][3]));
        }
        mx0 = fmaxf(mx0, __shfl_xor_sync(0xffffffffu, mx0, 1));
        mx0 = fmaxf(mx0, __shfl_xor_sync(0xffffffffu, mx0, 2));
        mx1 = fmaxf(mx1, __shfl_xor_sync(0xffffffffu, mx1, 1));
        mx1 = fmaxf(mx1, __shfl_xor_sync(0xffffffffu, mx1, 2));

        float mn0 = fmaxf(m0r, mx0);
        float mn1 = fmaxf(m1r, mx1);

        float sum0 = 0.f, sum1 = 0.f;
        #pragma unroll
        for (int nt = 0; nt < 8; nt++) {
            s[nt][0] = __expf(s[nt][0] - mn0);
            s[nt][1] = __expf(s[nt][1] - mn0);
            s[nt][2] = __expf(s[nt][2] - mn1);
            s[nt][3] = __expf(s[nt][3] - mn1);
            sum0 += s[nt][0] + s[nt][1];
            sum1 += s[nt][2] + s[nt][3];
        }
        sum0 += __shfl_xor_sync(0xffffffffu, sum0, 1);
        sum0 += __shfl_xor_sync(0xffffffffu, sum0, 2);
        sum1 += __shfl_xor_sync(0xffffffffu, sum1, 1);
        sum1 += __shfl_xor_sync(0xffffffffu, sum1, 2);

        float a0 = __expf(m0r - mn0);
        float a1 = __expf(m1r - mn1);
        l0r = l0r * a0 + sum0;
        l1r = l1r * a1 + sum1;
        m0r = mn0; m1r = mn1;
        #pragma unroll
        for (int nt = 0; nt < 8; nt++) {
            o[nt][0] *= a0; o[nt][1] *= a0;
            o[nt][2] *= a1; o[nt][3] *= a1;
        }

        // ---- PV: C-frag -> A-frag via quad shuffles, then mma ----
        const int src  = (lane & ~3) | (l4 >> 1);
        const int src2 = src + 2;
        const bool odd = (l4 & 1);
        #pragma unroll
        for (int kk = 0; kk < 8; kk++) {
            float v00 = __shfl_sync(0xffffffffu, s[kk][0], src);
            float v01 = __shfl_sync(0xffffffffu, s[kk][1], src);
            float v10 = __shfl_sync(0xffffffffu, s[kk][2], src);
            float v11 = __shfl_sync(0xffffffffu, s[kk][3], src);
            float w00 = __shfl_sync(0xffffffffu, s[kk][0], src2);
            float w01 = __shfl_sync(0xffffffffu, s[kk][1], src2);
            float w10 = __shfl_sync(0xffffffffu, s[kk][2], src2);
            float w11 = __shfl_sync(0xffffffffu, s[kk][3], src2);
            unsigned pa[4];
            pa[0] = f2tf(odd ? v01 : v00);
            pa[1] = f2tf(odd ? v11 : v10);
            pa[2] = f2tf(odd ? w01 : w00);
            pa[3] = f2tf(odd ? w11 : w10);

            const int c = kk * 8 + l4;
            #pragma unroll
            for (int nt = 0; nt < 8; nt++) {
                unsigned b0 = Vs[c][nt*8 + g];       // V[kpos=c][d=nt*8+g]
                unsigned b1 = Vs[c + 4][nt*8 + g];
                mma_tf32(o[nt], pa, b0, b1, o[nt]);
            }
        }
    }

    // ---- normalize + write ctx ----
    float inv0 = 1.f / l0r;
    float inv1 = 1.f / l1r;
    #pragma unroll
    for (int nt = 0; nt < 8; nt++) {
        int d = h * 64 + nt * 8 + l4 * 2;
        float2 r0v = make_float2(o[nt][0] * inv0, o[nt][1] * inv0);
        float2 r1v = make_float2(o[nt][2] * inv1, o[nt][3] * inv1);
        *(float2*)&outp[((size_t)b * S_ + q0 + r0    ) * DM_ + d] = r0v;
        *(float2*)&outp[((size_t)b * S_ + q0 + r0 + 8) * DM_ + d] = r1v;
    }
}

// --------------------------------------------------------------------------
extern "C" void kernel_launch(void* const* d_in, const int* in_sizes, int n_in,
                              void* d_out, int out_size)
{
    const float* hidden = (const float*)d_in[0];
    const float* mask   = (const float*)d_in[1];
    const int*   pos    = (const int*)  d_in[2];
    const float* Wq     = (const float*)d_in[3];
    const float* Wk     = (const float*)d_in[4];
    const float* Wv     = (const float*)d_in[5];
    float* out = (float*)d_out;

    const int gemm_smem = 6 * GSTG_WORDS * sizeof(unsigned);  // 61440 B
    cudaFuncSetAttribute(qkv_gemm,
                         cudaFuncAttributeMaxDynamicSharedMemorySize,
                         gemm_smem);

    prep_tf32<<<(B_*S_*DM_ + 255) / 256, 256>>>(hidden, Wq, Wk, Wv);

    dim3 g1(DM_ / 128, (B_ * S_) / 128, 3);
    qkv_gemm<<<g1, 256, gemm_smem>>>();

    int total_pairs = B_ * H_ * S_ * 32;
    rope_kernel<<<(total_pairs + 255) / 256, 256>>>(pos);

    dim3 g2(S_ / 64, H_, B_);
    attn_tf32<<<g2, 128>>>(mask, out);
}

// round 12
// speedup vs baseline: 1.8256x; 1.0665x over previous
#include <cuda_runtime.h>
#include <math.h>

#define B_  2
#define S_  2048
#define DM_ 1024
#define H_  16
#define D_  64

// Scratch. g_q/g_k: fp32 after gemm, tf32 bits after rope. g_v: tf32 bits.
__device__ float g_q[B_*H_*S_*D_];
__device__ float g_k[B_*H_*S_*D_];
__device__ float g_v[B_*H_*S_*D_];
// Pre-converted tf32 operands for the QKV gemm.
__device__ unsigned g_xt[B_*S_*DM_];      // hidden, tf32 bits
__device__ unsigned g_wt[3*DM_*DM_];      // Wq|Wk|Wv, tf32 bits

// --------------------------------------------------------------------------
__device__ __forceinline__ unsigned f2tf(float x) {
    unsigned u;
    asm("cvt.rna.tf32.f32 %0, %1;" : "=r"(u) : "f"(x));
    return u;
}

__device__ __forceinline__ void mma_tf32(float d[4], const unsigned a[4],
                                         unsigned b0, unsigned b1,
                                         const float c[4]) {
    asm volatile(
        "mma.sync.aligned.m16n8k8.row.col.f32.tf32.tf32.f32 "
        "{%0,%1,%2,%3}, {%4,%5,%6,%7}, {%8,%9}, {%10,%11,%12,%13};"
        : "=f"(d[0]), "=f"(d[1]), "=f"(d[2]), "=f"(d[3])
        : "r"(a[0]), "r"(a[1]), "r"(a[2]), "r"(a[3]),
          "r"(b0), "r"(b1),
          "f"(c[0]), "f"(c[1]), "f"(c[2]), "f"(c[3]));
}

// --------------------------------------------------------------------------
// Kernel 0: convert hidden + W to tf32 bits.
// --------------------------------------------------------------------------
__global__ __launch_bounds__(256)
void prep_tf32(const float* __restrict__ X,
               const float* __restrict__ Wq,
               const float* __restrict__ Wk,
               const float* __restrict__ Wv)
{
    int idx = blockIdx.x * blockDim.x + threadIdx.x;
    const int NX = B_*S_*DM_;       // 4M
    const int NW = DM_*DM_;         // 1M
    if (idx < NX) g_xt[idx] = f2tf(X[idx]);
    if (idx < NW) {
        g_wt[idx]        = f2tf(Wq[idx]);
        g_wt[NW + idx]   = f2tf(Wk[idx]);
        g_wt[2*NW + idx] = f2tf(Wv[idx]);
    }
}

// --------------------------------------------------------------------------
// Kernel 1: P[m,n] = sum_k X[m,k] * W[n,k], tf32 MMA (R8 structure,
// pre-converted inputs). 256 threads, 8 warps (4m x 2n), warp tile 32x64,
// k-step 32, single-buffered SMEM with register staging.
// V output (z==2) stored as tf32 bits.
// --------------------------------------------------------------------------
__global__ __launch_bounds__(256)
void qkv_gemm()
{
    __shared__ unsigned As[128][36];   // [m][k], pad 36
    __shared__ unsigned Bs[128][36];   // [n][k]

    const int z = blockIdx.z;
    float* out = (z == 0) ? g_q : (z == 1 ? g_k : g_v);
    const int isv = (z == 2);
    const unsigned* Wt = g_wt + (size_t)z * (DM_*DM_);

    const int tid  = threadIdx.x;
    const int lane = tid & 31;
    const int wid  = tid >> 5;
    const int wm   = wid & 3;        // m offset wm*32
    const int wn   = wid >> 2;       // n offset wn*64
    const int g    = lane >> 2;
    const int l4   = lane & 3;

    const int m0 = blockIdx.y * 128;
    const int n0 = blockIdx.x * 128;

    // gmem load mapping: row = tid>>1, word col = (tid&1)*16, 4x uint4
    const int lr = tid >> 1;
    const int lc = (tid & 1) * 16;
    const uint4* Ag = (const uint4*)(g_xt + (size_t)(m0 + lr) * DM_ + lc);
    const uint4* Bg = (const uint4*)(Wt   + (size_t)(n0 + lr) * DM_ + lc);

    float acc[2][8][4];
    #pragma unroll
    for (int mt = 0; mt < 2; mt++)
        #pragma unroll
        for (int nt = 0; nt < 8; nt++)
            #pragma unroll
            for (int i = 0; i < 4; i++) acc[mt][nt][i] = 0.f;

    for (int k0 = 0; k0 < DM_; k0 += 32) {
        uint4 av[4], bv[4];
        #pragma unroll
        for (int i = 0; i < 4; i++) {
            av[i] = Ag[(k0 >> 2) + i];
            bv[i] = Bg[(k0 >> 2) + i];
        }
        __syncthreads();   // previous compute done before overwrite
        #pragma unroll
        for (int i = 0; i < 4; i++) {
            *(uint4*)&As[lr][lc + i*4] = av[i];
            *(uint4*)&Bs[lr][lc + i*4] = bv[i];
        }
        __syncthreads();

        #pragma unroll
        for (int kk = 0; kk < 4; kk++) {
            const int c = kk * 8 + l4;
            unsigned a[2][4];
            #pragma unroll
            for (int mt = 0; mt < 2; mt++) {
                int r = wm * 32 + mt * 16 + g;
                a[mt][0] = As[r][c];
                a[mt][1] = As[r + 8][c];
                a[mt][2] = As[r][c + 4];
                a[mt][3] = As[r + 8][c + 4];
            }
            #pragma unroll
            for (int nt = 0; nt < 8; nt++) {
                int n = wn * 64 + nt * 8 + g;
                unsigned b0 = Bs[n][c];
                unsigned b1 = Bs[n][c + 4];
                mma_tf32(acc[0][nt], a[0], b0, b1, acc[0][nt]);
                mma_tf32(acc[1][nt], a[1], b0, b1, acc[1][nt]);
            }
        }
    }

    // Epilogue: scatter to [B,H,S,D]; V as tf32 bits.
    #pragma unroll
    for (int mt = 0; mt < 2; mt++) {
        #pragma unroll
        for (int half = 0; half < 2; half++) {
            int mm = m0 + wm * 32 + mt * 16 + g + half * 8;
            int bb = mm >> 11;
            int ss = mm & (S_ - 1);
            #pragma unroll
            for (int nt = 0; nt < 8; nt++) {
                int n  = n0 + wn * 64 + nt * 8 + l4 * 2;
                int hh = n >> 6;
                int dd = n & 63;
                float v0 = acc[mt][nt][half*2 + 0];
                float v1 = acc[mt][nt][half*2 + 1];
                float2 v;
                if (isv) v = make_float2(__uint_as_float(f2tf(v0)),
                                         __uint_as_float(f2tf(v1)));
                else     v = make_float2(v0, v1);
                *(float2*)&out[(((size_t)(bb*H_ + hh))*S_ + ss)*D_ + dd] = v;
            }
        }
    }
}

// --------------------------------------------------------------------------
// Kernel 2: RoPE in-place on g_q/g_k; Q scaled by 1/8; outputs tf32 bits.
// --------------------------------------------------------------------------
__global__ __launch_bounds__(256)
void rope_kernel(const int* __restrict__ pos_ids)
{
    int idx = blockIdx.x * blockDim.x + threadIdx.x;
    const int total = B_ * H_ * S_ * 32;
    if (idx >= total) return;

    int d2 = idx & 31;
    int s  = (idx >> 5) & (S_ - 1);
    int b  = idx >> 20;

    int pos = pos_ids[b * S_ + s];
    float inv = (float)exp(-(double)d2 * (log(10000.0) / 32.0));
    float ang = (float)pos * inv;
    float sn, cs;
    sincosf(ang, &sn, &cs);

    int base = (idx >> 5) << 6;

    float q1 = g_q[base + d2];
    float q2 = g_q[base + 32 + d2];
    g_q[base + d2]      = __uint_as_float(f2tf(0.125f * (q1 * cs - q2 * sn)));
    g_q[base + 32 + d2] = __uint_as_float(f2tf(0.125f * (q2 * cs + q1 * sn)));

    float k1 = g_k[base + d2];
    float k2 = g_k[base + 32 + d2];
    g_k[base + d2]      = __uint_as_float(f2tf(k1 * cs - k2 * sn));
    g_k[base + 32 + d2] = __uint_as_float(f2tf(k2 * cs + k1 * sn));
}

// --------------------------------------------------------------------------
// Kernel 3: flash attention, tf32 MMA, mt=2 (32 q-rows per warp).
// 128 threads (4 warps), q-tile 128, k-tile 64. Every K/V B-fragment is
// shared across two mma's -> SMEM bytes per mma halved vs R11.
// Ks[kpos][d] pad 68 (QK B-frag conflict-free: bank 4g+l4).
// Vs[kpos][d] pad 72 (PV B-frag conflict-free: bank 8*l4+g).
// P stays in registers via quad-shuffle transpose. SMEM 35840 B.
// --------------------------------------------------------------------------
__global__ __launch_bounds__(128)
void attn_tf32(const float* __restrict__ mask, float* __restrict__ outp)
{
    __shared__ unsigned Ks[64][68];
    __shared__ unsigned Vs[64][72];

    const int tid  = threadIdx.x;
    const int lane = tid & 31;
    const int wid  = tid >> 5;
    const int g    = lane >> 2;
    const int l4   = lane & 3;

    const int b  = blockIdx.z;
    const int h  = blockIdx.y;
    const int q0 = blockIdx.x * 128;
    const int wb = wid * 32;           // warp's q-row base (local)

    const unsigned* Qg = (const unsigned*)g_q
                         + (((size_t)(b*H_ + h))*S_ + q0 + wb) * D_;
    const uint4* Kg4 = (const uint4*)(g_k + (((size_t)(b*H_ + h))*S_) * D_);
    const uint4* Vg4 = (const uint4*)(g_v + (((size_t)(b*H_ + h))*S_) * D_);
    const float* Mg  = mask + ((size_t)b * S_ + q0 + wb) * S_;

    // Q A-fragments for both 16-row tiles (already tf32 bits)
    unsigned qa[2][8][4];
    #pragma unroll
    for (int mt = 0; mt < 2; mt++) {
        int row0 = mt * 16 + g;
        #pragma unroll
        for (int kk = 0; kk < 8; kk++) {
            qa[mt][kk][0] = Qg[(size_t)row0      * D_ + kk*8 + l4];
            qa[mt][kk][1] = Qg[(size_t)(row0+8)  * D_ + kk*8 + l4];
            qa[mt][kk][2] = Qg[(size_t)row0      * D_ + kk*8 + l4 + 4];
            qa[mt][kk][3] = Qg[(size_t)(row0+8)  * D_ + kk*8 + l4 + 4];
        }
    }

    float o[2][8][4];
    #pragma unroll
    for (int mt = 0; mt < 2; mt++)
        #pragma unroll
        for (int nt = 0; nt < 8; nt++)
            #pragma unroll
            for (int i = 0; i < 4; i++) o[mt][nt][i] = 0.f;
    float mrow[2][2], lrow[2][2];
    #pragma unroll
    for (int mt = 0; mt < 2; mt++) {
        mrow[mt][0] = -1e30f; mrow[mt][1] = -1e30f;
        lrow[mt][0] = 0.f;    lrow[mt][1] = 0.f;
    }

    const int kr   = tid & 63;      // K/V row
    const int half = tid >> 6;      // d half

    for (int t = 0; t < S_ / 64; t++) {
        const int kbase = t * 64;
        __syncthreads();
        {
            const uint4* Kp = Kg4 + (size_t)(kbase + kr) * (D_/4) + half * 8;
            const uint4* Vp = Vg4 + (size_t)(kbase + kr) * (D_/4) + half * 8;
            #pragma unroll
            for (int i = 0; i < 8; i++) {
                *(uint4*)&Ks[kr][half*32 + i*4] = Kp[i];
                *(uint4*)&Vs[kr][half*32 + i*4] = Vp[i];
            }
        }
        __syncthreads();

        // ---- S = Q K^T (both 16-row tiles share every B fragment) ----
        float s[2][8][4];
        #pragma unroll
        for (int mt = 0; mt < 2; mt++)
            #pragma unroll
            for (int nt = 0; nt < 8; nt++)
                #pragma unroll
                for (int i = 0; i < 4; i++) s[mt][nt][i] = 0.f;

        #pragma unroll
        for (int kk = 0; kk < 8; kk++) {
            const int c = kk * 8 + l4;
            #pragma unroll
            for (int nt = 0; nt < 8; nt++) {
                unsigned b0 = Ks[nt*8 + g][c];
                unsigned b1 = Ks[nt*8 + g][c + 4];
                mma_tf32(s[0][nt], qa[0][kk], b0, b1, s[0][nt]);
                mma_tf32(s[1][nt], qa[1][kk], b0, b1, s[1][nt]);
            }
        }

        // ---- mask add + online softmax per 16-row tile ----
        #pragma unroll
        for (int mt = 0; mt < 2; mt++) {
            #pragma unroll
            for (int nt = 0; nt < 8; nt++) {
                const float* mp = Mg + (size_t)(mt*16 + g) * S_
                                     + kbase + nt*8 + l4*2;
                float2 ma = *(const float2*)mp;
                float2 mb = *(const float2*)(mp + 8 * S_);
                s[mt][nt][0] += ma.x; s[mt][nt][1] += ma.y;
                s[mt][nt][2] += mb.x; s[mt][nt][3] += mb.y;
            }

            float mx0 = -1e30f, mx1 = -1e30f;
            #pragma unroll
            for (int nt = 0; nt < 8; nt++) {
                mx0 = fmaxf(mx0, fmaxf(s[mt][nt][0], s[mt][nt][1]));
                mx1 = fmaxf(mx1, fmaxf(s[mt][nt][2], s[mt][nt][3]));
            }
            mx0 = fmaxf(mx0, __shfl_xor_sync(0xffffffffu, mx0, 1));
            mx0 = fmaxf(mx0, __shfl_xor_sync(0xffffffffu, mx0, 2));
            mx1 = fmaxf(mx1, __shfl_xor_sync(0xffffffffu, mx1, 1));
            mx1 = fmaxf(mx1, __shfl_xor_sync(0xffffffffu, mx1, 2));

            float mn0 = fmaxf(mrow[mt][0], mx0);
            float mn1 = fmaxf(mrow[mt][1], mx1);

            float sum0 = 0.f, sum1 = 0.f;
            #pragma unroll
            for (int nt = 0; nt < 8; nt++) {
                s[mt][nt][0] = __expf(s[mt][nt][0] - mn0);
                s[mt][nt][1] = __expf(s[mt][nt][1] - mn0);
                s[mt][nt][2] = __expf(s[mt][nt][2] - mn1);
                s[mt][nt][3] = __expf(s[mt][nt][3] - mn1);
                sum0 += s[mt][nt][0] + s[mt][nt][1];
                sum1 += s[mt][nt][2] + s[mt][nt][3];
            }
            sum0 += __shfl_xor_sync(0xffffffffu, sum0, 1);
            sum0 += __shfl_xor_sync(0xffffffffu, sum0, 2);
            sum1 += __shfl_xor_sync(0xffffffffu, sum1, 1);
            sum1 += __shfl_xor_sync(0xffffffffu, sum1, 2);

            float a0 = __expf(mrow[mt][0] - mn0);
            float a1 = __expf(mrow[mt][1] - mn1);
            lrow[mt][0] = lrow[mt][0] * a0 + sum0;
            lrow[mt][1] = lrow[mt][1] * a1 + sum1;
            mrow[mt][0] = mn0; mrow[mt][1] = mn1;
            #pragma unroll
            for (int nt = 0; nt < 8; nt++) {
                o[mt][nt][0] *= a0; o[mt][nt][1] *= a0;
                o[mt][nt][2] *= a1; o[mt][nt][3] *= a1;
            }
        }

        // ---- PV: C-frag -> A-frag via quad shuffles; V frags shared ----
        const int src  = (lane & ~3) | (l4 >> 1);
        const int src2 = src + 2;
        const bool odd = (l4 & 1);
        #pragma unroll
        for (int kk = 0; kk < 8; kk++) {
            unsigned pa[2][4];
            #pragma unroll
            for (int mt = 0; mt < 2; mt++) {
                float v00 = __shfl_sync(0xffffffffu, s[mt][kk][0], src);
                float v01 = __shfl_sync(0xffffffffu, s[mt][kk][1], src);
                float v10 = __shfl_sync(0xffffffffu, s[mt][kk][2], src);
                float v11 = __shfl_sync(0xffffffffu, s[mt][kk][3], src);
                float w00 = __shfl_sync(0xffffffffu, s[mt][kk][0], src2);
                float w01 = __shfl_sync(0xffffffffu, s[mt][kk][1], src2);
                float w10 = __shfl_sync(0xffffffffu, s[mt][kk][2], src2);
                float w11 = __shfl_sync(0xffffffffu, s[mt][kk][3], src2);
                pa[mt][0] = f2tf(odd ? v01 : v00);
                pa[mt][1] = f2tf(odd ? v11 : v10);
                pa[mt][2] = f2tf(odd ? w01 : w00);
                pa[mt][3] = f2tf(odd ? w11 : w10);
            }
            const int c = kk * 8 + l4;
            #pragma unroll
            for (int nt = 0; nt < 8; nt++) {
                unsigned b0 = Vs[c][nt*8 + g];
                unsigned b1 = Vs[c + 4][nt*8 + g];
                mma_tf32(o[0][nt], pa[0], b0, b1, o[0][nt]);
                mma_tf32(o[1][nt], pa[1], b0, b1, o[1][nt]);
            }
        }
    }

    // ---- normalize + write ctx ----
    #pragma unroll
    for (int mt = 0; mt < 2; mt++) {
        float inv0 = 1.f / lrow[mt][0];
        float inv1 = 1.f / lrow[mt][1];
        int row0 = q0 + wb + mt * 16 + g;
        #pragma unroll
        for (int nt = 0; nt < 8; nt++) {
            int d = h * 64 + nt * 8 + l4 * 2;
            float2 r0v = make_float2(o[mt][nt][0] * inv0, o[mt][nt][1] * inv0);
            float2 r1v = make_float2(o[mt][nt][2] * inv1, o[mt][nt][3] * inv1);
            *(float2*)&outp[((size_t)b * S_ + row0    ) * DM_ + d] = r0v;
            *(float2*)&outp[((size_t)b * S_ + row0 + 8) * DM_ + d] = r1v;
        }
    }
}

// --------------------------------------------------------------------------
extern "C" void kernel_launch(void* const* d_in, const int* in_sizes, int n_in,
                              void* d_out, int out_size)
{
    const float* hidden = (const float*)d_in[0];
    const float* mask   = (const float*)d_in[1];
    const int*   pos    = (const int*)  d_in[2];
    const float* Wq     = (const float*)d_in[3];
    const float* Wk     = (const float*)d_in[4];
    const float* Wv     = (const float*)d_in[5];
    float* out = (float*)d_out;

    prep_tf32<<<(B_*S_*DM_ + 255) / 256, 256>>>(hidden, Wq, Wk, Wv);

    dim3 g1(DM_ / 128, (B_ * S_) / 128, 3);
    qkv_gemm<<<g1, 256>>>();

    int total_pairs = B_ * H_ * S_ * 32;
    rope_kernel<<<(total_pairs + 255) / 256, 256>>>(pos);

    dim3 g2(S_ / 128, H_, B_);
    attn_tf32<<<g2, 128>>>(mask, out);
}

// round 13
// speedup vs baseline: 1.9923x; 1.0913x over previous
#include <cuda_runtime.h>
#include <math.h>

#define B_  2
#define S_  2048
#define DM_ 1024
#define H_  16
#define D_  64

// Scratch. g_q/g_k: fp32 after gemm, tf32 bits after rope. g_v: tf32 bits.
__device__ float g_q[B_*H_*S_*D_];
__device__ float g_k[B_*H_*S_*D_];
__device__ float g_v[B_*H_*S_*D_];

// --------------------------------------------------------------------------
__device__ __forceinline__ unsigned f2tf(float x) {
    unsigned u;
    asm("cvt.rna.tf32.f32 %0, %1;" : "=r"(u) : "f"(x));
    return u;
}

__device__ __forceinline__ void mma_tf32(float d[4], const unsigned a[4],
                                         unsigned b0, unsigned b1,
                                         const float c[4]) {
    asm volatile(
        "mma.sync.aligned.m16n8k8.row.col.f32.tf32.tf32.f32 "
        "{%0,%1,%2,%3}, {%4,%5,%6,%7}, {%8,%9}, {%10,%11,%12,%13};"
        : "=f"(d[0]), "=f"(d[1]), "=f"(d[2]), "=f"(d[3])
        : "r"(a[0]), "r"(a[1]), "r"(a[2]), "r"(a[3]),
          "r"(b0), "r"(b1),
          "f"(c[0]), "f"(c[1]), "f"(c[2]), "f"(c[3]));
}

__device__ __forceinline__ void cp_async16(unsigned saddr, const void* gptr) {
    asm volatile("cp.async.cg.shared.global [%0], [%1], 16;"
                 :: "r"(saddr), "l"(gptr));
}

// --------------------------------------------------------------------------
// Kernel 1: P[m,n] = sum_k X[m,k] * W[n,k], tf32 MMA (exact R8 structure —
// measured 250us). 256 threads, 8 warps (4m x 2n), warp tile 32x64, k-step
// 32, in-loop f2tf, scalar SMEM stores. V output (z==2) stored as tf32 bits.
// --------------------------------------------------------------------------
__global__ __launch_bounds__(256)
void qkv_gemm(const float* __restrict__ X,
              const float* __restrict__ Wq,
              const float* __restrict__ Wk,
              const float* __restrict__ Wv)
{
    __shared__ unsigned As[128][36];   // [m][k], tf32 bits, pad 36 for banks
    __shared__ unsigned Bs[128][36];   // [n][k]

    const float* W;
    float* out;
    int isv = 0;
    if (blockIdx.z == 0)      { W = Wq; out = g_q; }
    else if (blockIdx.z == 1) { W = Wk; out = g_k; }
    else                      { W = Wv; out = g_v; isv = 1; }

    const int tid  = threadIdx.x;
    const int lane = tid & 31;
    const int wid  = tid >> 5;
    const int wm   = wid & 3;        // 0..3 -> m offset wm*32
    const int wn   = wid >> 2;       // 0..1 -> n offset wn*64
    const int g    = lane >> 2;      // group id 0..7
    const int l4   = lane & 3;       // thread in group 0..3

    const int m0 = blockIdx.y * 128;
    const int n0 = blockIdx.x * 128;

    // gmem load mapping: row = tid>>1 (0..127), 4 float4 at cols (tid&1)*16+i*4
    const int lr = tid >> 1;
    const int lc = (tid & 1) * 16;
    const float* Ap = X + (size_t)(m0 + lr) * DM_ + lc;
    const float* Bp = W + (size_t)(n0 + lr) * DM_ + lc;

    float acc[2][8][4];
    #pragma unroll
    for (int mt = 0; mt < 2; mt++)
        #pragma unroll
        for (int nt = 0; nt < 8; nt++)
            #pragma unroll
            for (int i = 0; i < 4; i++) acc[mt][nt][i] = 0.f;

    for (int k0 = 0; k0 < DM_; k0 += 32) {
        float4 av[4], bv[4];
        #pragma unroll
        for (int i = 0; i < 4; i++) {
            av[i] = *(const float4*)(Ap + k0 + i * 4);
            bv[i] = *(const float4*)(Bp + k0 + i * 4);
        }
        __syncthreads();
        #pragma unroll
        for (int i = 0; i < 4; i++) {
            As[lr][lc + i*4 + 0] = f2tf(av[i].x);
            As[lr][lc + i*4 + 1] = f2tf(av[i].y);
            As[lr][lc + i*4 + 2] = f2tf(av[i].z);
            As[lr][lc + i*4 + 3] = f2tf(av[i].w);
            Bs[lr][lc + i*4 + 0] = f2tf(bv[i].x);
            Bs[lr][lc + i*4 + 1] = f2tf(bv[i].y);
            Bs[lr][lc + i*4 + 2] = f2tf(bv[i].z);
            Bs[lr][lc + i*4 + 3] = f2tf(bv[i].w);
        }
        __syncthreads();

        #pragma unroll
        for (int kk = 0; kk < 4; kk++) {
            const int c = kk * 8 + l4;
            unsigned a[2][4];
            #pragma unroll
            for (int mt = 0; mt < 2; mt++) {
                int r = wm * 32 + mt * 16 + g;
                a[mt][0] = As[r][c];
                a[mt][1] = As[r + 8][c];
                a[mt][2] = As[r][c + 4];
                a[mt][3] = As[r + 8][c + 4];
            }
            #pragma unroll
            for (int nt = 0; nt < 8; nt++) {
                int n = wn * 64 + nt * 8 + g;
                unsigned b0 = Bs[n][c];
                unsigned b1 = Bs[n][c + 4];
                mma_tf32(acc[0][nt], a[0], b0, b1, acc[0][nt]);
                mma_tf32(acc[1][nt], a[1], b0, b1, acc[1][nt]);
            }
        }
    }

    // Epilogue: scatter to [B,H,S,D]; V as tf32 bits (out of hot loop).
    #pragma unroll
    for (int mt = 0; mt < 2; mt++) {
        #pragma unroll
        for (int half = 0; half < 2; half++) {
            int mm = m0 + wm * 32 + mt * 16 + g + half * 8;
            int bb = mm >> 11;
            int ss = mm & (S_ - 1);
            #pragma unroll
            for (int nt = 0; nt < 8; nt++) {
                int n  = n0 + wn * 64 + nt * 8 + l4 * 2;
                int hh = n >> 6;
                int dd = n & 63;
                float v0 = acc[mt][nt][half*2 + 0];
                float v1 = acc[mt][nt][half*2 + 1];
                float2 v;
                if (isv) v = make_float2(__uint_as_float(f2tf(v0)),
                                         __uint_as_float(f2tf(v1)));
                else     v = make_float2(v0, v1);
                *(float2*)&out[(((size_t)(bb*H_ + hh))*S_ + ss)*D_ + dd] = v;
            }
        }
    }
}

// --------------------------------------------------------------------------
// Kernel 2: RoPE in-place on g_q/g_k; Q scaled by 1/8; outputs tf32 bits.
// --------------------------------------------------------------------------
__global__ __launch_bounds__(256)
void rope_kernel(const int* __restrict__ pos_ids)
{
    int idx = blockIdx.x * blockDim.x + threadIdx.x;
    const int total = B_ * H_ * S_ * 32;
    if (idx >= total) return;

    int d2 = idx & 31;
    int s  = (idx >> 5) & (S_ - 1);
    int b  = idx >> 20;

    int pos = pos_ids[b * S_ + s];
    float inv = (float)exp(-(double)d2 * (log(10000.0) / 32.0));
    float ang = (float)pos * inv;
    float sn, cs;
    sincosf(ang, &sn, &cs);

    int base = (idx >> 5) << 6;

    float q1 = g_q[base + d2];
    float q2 = g_q[base + 32 + d2];
    g_q[base + d2]      = __uint_as_float(f2tf(0.125f * (q1 * cs - q2 * sn)));
    g_q[base + 32 + d2] = __uint_as_float(f2tf(0.125f * (q2 * cs + q1 * sn)));

    float k1 = g_k[base + d2];
    float k2 = g_k[base + 32 + d2];
    g_k[base + d2]      = __uint_as_float(f2tf(k1 * cs - k2 * sn));
    g_k[base + 32 + d2] = __uint_as_float(f2tf(k2 * cs + k1 * sn));
}

// --------------------------------------------------------------------------
// Kernel 3: flash attention, tf32 MMA, mt=2, cp.async double-buffered K/V.
// 128 threads (4 warps), q-tile 128, k-tile 64.
// Ks[kpos][d] pad 68 (QK B-frag bank 4g+l4, conflict-free).
// Vs[kpos][d] pad 72 (PV B-frag bank 8*l4+g, conflict-free).
// Dynamic SMEM: 2*(64*68 + 64*72)*4 = 71680 B. Occupancy is register-
// limited (2 CTAs/SM), so the double buffer costs nothing.
// --------------------------------------------------------------------------
#define K_WORDS (64 * 68)
#define V_WORDS (64 * 72)
#define ATTN_SMEM ((2 * K_WORDS + 2 * V_WORDS) * 4)

__global__ __launch_bounds__(128)
void attn_tf32(const float* __restrict__ mask, float* __restrict__ outp)
{
    extern __shared__ unsigned sm[];   // K0 | K1 | V0 | V1

    const int tid  = threadIdx.x;
    const int lane = tid & 31;
    const int wid  = tid >> 5;
    const int g    = lane >> 2;
    const int l4   = lane & 3;

    const int b  = blockIdx.z;
    const int h  = blockIdx.y;
    const int q0 = blockIdx.x * 128;
    const int wb = wid * 32;           // warp's q-row base (local)

    const unsigned* Qg = (const unsigned*)g_q
                         + (((size_t)(b*H_ + h))*S_ + q0 + wb) * D_;
    const uint4* Kg4 = (const uint4*)(g_k + (((size_t)(b*H_ + h))*S_) * D_);
    const uint4* Vg4 = (const uint4*)(g_v + (((size_t)(b*H_ + h))*S_) * D_);
    const float* Mg  = mask + ((size_t)b * S_ + q0 + wb) * S_;

    // Q A-fragments for both 16-row tiles (already tf32 bits)
    unsigned qa[2][8][4];
    #pragma unroll
    for (int mt = 0; mt < 2; mt++) {
        int row0 = mt * 16 + g;
        #pragma unroll
        for (int kk = 0; kk < 8; kk++) {
            qa[mt][kk][0] = Qg[(size_t)row0      * D_ + kk*8 + l4];
            qa[mt][kk][1] = Qg[(size_t)(row0+8)  * D_ + kk*8 + l4];
            qa[mt][kk][2] = Qg[(size_t)row0      * D_ + kk*8 + l4 + 4];
            qa[mt][kk][3] = Qg[(size_t)(row0+8)  * D_ + kk*8 + l4 + 4];
        }
    }

    float o[2][8][4];
    #pragma unroll
    for (int mt = 0; mt < 2; mt++)
        #pragma unroll
        for (int nt = 0; nt < 8; nt++)
            #pragma unroll
            for (int i = 0; i < 4; i++) o[mt][nt][i] = 0.f;
    float mrow[2][2], lrow[2][2];
    #pragma unroll
    for (int mt = 0; mt < 2; mt++) {
        mrow[mt][0] = -1e30f; mrow[mt][1] = -1e30f;
        lrow[mt][0] = 0.f;    lrow[mt][1] = 0.f;
    }

    // cp.async mapping: kr = tid&63 (row), half = tid>>6 (d half), 8x16B each
    const int kr   = tid & 63;
    const int half = tid >> 6;
    const unsigned sbase = (unsigned)__cvta_generic_to_shared(sm);
    const unsigned kOff = sbase + (unsigned)(kr * 68 + half * 32) * 4u;
    const unsigned vOff = sbase + (unsigned)(2 * K_WORDS + kr * 72 + half * 32) * 4u;
    const int gOff = kr * (D_/4) + half * 8;

    // prologue: tile 0 -> buffer 0
    #pragma unroll
    for (int i = 0; i < 8; i++) {
        cp_async16(kOff + i*16, Kg4 + gOff + i);
        cp_async16(vOff + i*16, Vg4 + gOff + i);
    }
    asm volatile("cp.async.commit_group;");

    const int NT = S_ / 64;
    for (int t = 0; t < NT; t++) {
        if (t + 1 < NT) {
            unsigned kb = (unsigned)((t + 1) & 1);
            unsigned ka = kOff + kb * K_WORDS * 4u;
            unsigned va = vOff + kb * V_WORDS * 4u;
            int go = gOff + (t + 1) * 64 * (D_/4);
            #pragma unroll
            for (int i = 0; i < 8; i++) {
                cp_async16(ka + i*16, Kg4 + go + i);
                cp_async16(va + i*16, Vg4 + go + i);
            }
        }
        asm volatile("cp.async.commit_group;");
        asm volatile("cp.async.wait_group 1;");
        __syncthreads();

        const unsigned* Kp = sm + (t & 1) * K_WORDS;
        const unsigned* Vp = sm + 2 * K_WORDS + (t & 1) * V_WORDS;
        const int kbase = t * 64;

        // ---- S = Q K^T (both 16-row tiles share every B fragment) ----
        float s[2][8][4];
        #pragma unroll
        for (int mt = 0; mt < 2; mt++)
            #pragma unroll
            for (int nt = 0; nt < 8; nt++)
                #pragma unroll
                for (int i = 0; i < 4; i++) s[mt][nt][i] = 0.f;

        #pragma unroll
        for (int kk = 0; kk < 8; kk++) {
            const int c = kk * 8 + l4;
            #pragma unroll
            for (int nt = 0; nt < 8; nt++) {
                unsigned b0 = Kp[(nt*8 + g) * 68 + c];
                unsigned b1 = Kp[(nt*8 + g) * 68 + c + 4];
                mma_tf32(s[0][nt], qa[0][kk], b0, b1, s[0][nt]);
                mma_tf32(s[1][nt], qa[1][kk], b0, b1, s[1][nt]);
            }
        }

        // ---- mask add + online softmax per 16-row tile ----
        #pragma unroll
        for (int mt = 0; mt < 2; mt++) {
            #pragma unroll
            for (int nt = 0; nt < 8; nt++) {
                const float* mp = Mg + (size_t)(mt*16 + g) * S_
                                     + kbase + nt*8 + l4*2;
                float2 ma = *(const float2*)mp;
                float2 mb = *(const float2*)(mp + 8 * S_);
                s[mt][nt][0] += ma.x; s[mt][nt][1] += ma.y;
                s[mt][nt][2] += mb.x; s[mt][nt][3] += mb.y;
            }

            float mx0 = -1e30f, mx1 = -1e30f;
            #pragma unroll
            for (int nt = 0; nt < 8; nt++) {
                mx0 = fmaxf(mx0, fmaxf(s[mt][nt][0], s[mt][nt][1]));
                mx1 = fmaxf(mx1, fmaxf(s[mt][nt][2], s[mt][nt][3]));
            }
            mx0 = fmaxf(mx0, __shfl_xor_sync(0xffffffffu, mx0, 1));
            mx0 = fmaxf(mx0, __shfl_xor_sync(0xffffffffu, mx0, 2));
            mx1 = fmaxf(mx1, __shfl_xor_sync(0xffffffffu, mx1, 1));
            mx1 = fmaxf(mx1, __shfl_xor_sync(0xffffffffu, mx1, 2));

            float mn0 = fmaxf(mrow[mt][0], mx0);
            float mn1 = fmaxf(mrow[mt][1], mx1);

            float sum0 = 0.f, sum1 = 0.f;
            #pragma unroll
            for (int nt = 0; nt < 8; nt++) {
                s[mt][nt][0] = __expf(s[mt][nt][0] - mn0);
                s[mt][nt][1] = __expf(s[mt][nt][1] - mn0);
                s[mt][nt][2] = __expf(s[mt][nt][2] - mn1);
                s[mt][nt][3] = __expf(s[mt][nt][3] - mn1);
                sum0 += s[mt][nt][0] + s[mt][nt][1];
                sum1 += s[mt][nt][2] + s[mt][nt][3];
            }
            sum0 += __shfl_xor_sync(0xffffffffu, sum0, 1);
            sum0 += __shfl_xor_sync(0xffffffffu, sum0, 2);
            sum1 += __shfl_xor_sync(0xffffffffu, sum1, 1);
            sum1 += __shfl_xor_sync(0xffffffffu, sum1, 2);

            float a0 = __expf(mrow[mt][0] - mn0);
            float a1 = __expf(mrow[mt][1] - mn1);
            lrow[mt][0] = lrow[mt][0] * a0 + sum0;
            lrow[mt][1] = lrow[mt][1] * a1 + sum1;
            mrow[mt][0] = mn0; mrow[mt][1] = mn1;
            #pragma unroll
            for (int nt = 0; nt < 8; nt++) {
                o[mt][nt][0] *= a0; o[mt][nt][1] *= a0;
                o[mt][nt][2] *= a1; o[mt][nt][3] *= a1;
            }
        }

        // ---- PV: C-frag -> A-frag via quad shuffles; V frags shared ----
        const int src  = (lane & ~3) | (l4 >> 1);
        const int src2 = src + 2;
        const bool odd = (l4 & 1);
        #pragma unroll
        for (int kk = 0; kk < 8; kk++) {
            unsigned pa[2][4];
            #pragma unroll
            for (int mt = 0; mt < 2; mt++) {
                float v00 = __shfl_sync(0xffffffffu, s[mt][kk][0], src);
                float v01 = __shfl_sync(0xffffffffu, s[mt][kk][1], src);
                float v10 = __shfl_sync(0xffffffffu, s[mt][kk][2], src);
                float v11 = __shfl_sync(0xffffffffu, s[mt][kk][3], src);
                float w00 = __shfl_sync(0xffffffffu, s[mt][kk][0], src2);
                float w01 = __shfl_sync(0xffffffffu, s[mt][kk][1], src2);
                float w10 = __shfl_sync(0xffffffffu, s[mt][kk][2], src2);
                float w11 = __shfl_sync(0xffffffffu, s[mt][kk][3], src2);
                pa[mt][0] = f2tf(odd ? v01 : v00);
                pa[mt][1] = f2tf(odd ? v11 : v10);
                pa[mt][2] = f2tf(odd ? w01 : w00);
                pa[mt][3] = f2tf(odd ? w11 : w10);
            }
            const int c = kk * 8 + l4;
            #pragma unroll
            for (int nt = 0; nt < 8; nt++) {
                unsigned b0 = Vp[c * 72 + nt*8 + g];
                unsigned b1 = Vp[(c + 4) * 72 + nt*8 + g];
                mma_tf32(o[0][nt], pa[0], b0, b1, o[0][nt]);
                mma_tf32(o[1][nt], pa[1], b0, b1, o[1][nt]);
            }
        }
        __syncthreads();   // buffer reads done before t+2 overwrites it
    }

    // ---- normalize + write ctx ----
    #pragma unroll
    for (int mt = 0; mt < 2; mt++) {
        float inv0 = 1.f / lrow[mt][0];
        float inv1 = 1.f / lrow[mt][1];
        int row0 = q0 + wb + mt * 16 + g;
        #pragma unroll
        for (int nt = 0; nt < 8; nt++) {
            int d = h * 64 + nt * 8 + l4 * 2;
            float2 r0v = make_float2(o[mt][nt][0] * inv0, o[mt][nt][1] * inv0);
            float2 r1v = make_float2(o[mt][nt][2] * inv1, o[mt][nt][3] * inv1);
            *(float2*)&outp[((size_t)b * S_ + row0    ) * DM_ + d] = r0v;
            *(float2*)&outp[((size_t)b * S_ + row0 + 8) * DM_ + d] = r1v;
        }
    }
}

// --------------------------------------------------------------------------
extern "C" void kernel_launch(void* const* d_in, const int* in_sizes, int n_in,
                              void* d_out, int out_size)
{
    const float* hidden = (const float*)d_in[0];
    const float* mask   = (const float*)d_in[1];
    const int*   pos    = (const int*)  d_in[2];
    const float* Wq     = (const float*)d_in[3];
    const float* Wk     = (const float*)d_in[4];
    const float* Wv     = (const float*)d_in[5];
    float* out = (float*)d_out;

    cudaFuncSetAttribute(attn_tf32,
                         cudaFuncAttributeMaxDynamicSharedMemorySize,
                         ATTN_SMEM);

    dim3 g1(DM_ / 128, (B_ * S_) / 128, 3);
    qkv_gemm<<<g1, 256>>>(hidden, Wq, Wk, Wv);

    int total_pairs = B_ * H_ * S_ * 32;
    rope_kernel<<<(total_pairs + 255) / 256, 256>>>(pos);

    dim3 g2(S_ / 128, H_, B_);
    attn_tf32<<<g2, 128, ATTN_SMEM>>>(mask, out);
}